// round 9
// baseline (speedup 1.0000x reference)
#include <cuda_runtime.h>
#include <cstdint>

#define B_   32
#define T_   2048
#define XD   64
#define ZD   128
#define TAU  16

// ---------------- scratch (device globals; no allocations allowed) ----------
__device__ float g_Vx[16][64][64];      // [k][d][i]
__device__ float g_Vz[16][128][64];     // [k][e][i]
__device__ float g_VzSS[16][128][64];   // suffix sums over k ; [0] = full sum
__device__ float g_C[16][64];
__device__ float g_CSS[16][64];

// ---------------- packed f32x2 helpers --------------------------------------
typedef unsigned long long u64;
union F2U { u64 u; float2 f; };

__device__ __forceinline__ u64 pack2(float x) {
    u64 d;
    asm("mov.b64 %0, {%1, %1};" : "=l"(d) : "f"(x));
    return d;
}
__device__ __forceinline__ u64 ffma2(u64 a, u64 b, u64 c) {
    u64 d;
    asm("fma.rn.f32x2 %0, %1, %2, %3;" : "=l"(d) : "l"(a), "l"(b), "l"(c));
    return d;
}

// =============================================================================
// Kernel 1: v = W1@W2 (over h), c = b1@W2 + b2. Reads W1 once. NO copy here —
// the 800MB transpose-copy is fused into main_kernel's idle memory pipeline.
// =============================================================================
__global__ __launch_bounds__(256) void vc_kernel(
    const float* __restrict__ W1, const float* __restrict__ b1,
    const float* __restrict__ W2, const float* __restrict__ b2)
{
    __shared__ float s_w2[512];
    int blk = blockIdx.x;              // = i*16 + k
    int i = blk >> 4, k = blk & 15;
    const float* src = W1 + (size_t)blk * (192 * 512);
    const float* w2p = W2 + (size_t)blk * 512;

    for (int j = threadIdx.x; j < 512; j += 256) s_w2[j] = w2p[j];
    __syncthreads();

    int warp = threadIdx.x >> 5, lane = threadIdx.x & 31;

    float w2r[4][4];
    #pragma unroll
    for (int j = 0; j < 4; j++) {
        int q = lane + 32 * j;
        #pragma unroll
        for (int c = 0; c < 4; c++) w2r[j][c] = s_w2[q * 4 + c];
    }

    for (int d = warp; d < 192; d += 8) {
        const float4* s4 = (const float4*)(src + (size_t)d * 512);
        float acc = 0.f;
        #pragma unroll
        for (int j = 0; j < 4; j++) {
            int q = lane + 32 * j;
            float4 v = s4[q];
            acc += v.x * w2r[j][0] + v.y * w2r[j][1]
                 + v.z * w2r[j][2] + v.w * w2r[j][3];
        }
        #pragma unroll
        for (int o = 16; o; o >>= 1) acc += __shfl_xor_sync(0xffffffffu, acc, o);
        if (lane == 0) {
            if (d < 64) g_Vx[k][d][i] = acc;
            else        g_Vz[k][d - 64][i] = acc;
        }
    }

    if (warp == 0) {
        const float* b1p = b1 + (size_t)blk * 512;
        float acc = 0.f;
        for (int j = lane; j < 512; j += 32) acc += b1p[j] * s_w2[j];
        #pragma unroll
        for (int o = 16; o; o >>= 1) acc += __shfl_xor_sync(0xffffffffu, acc, o);
        if (lane == 0) g_C[k][i] = acc + b2[blk];
    }
}

// =============================================================================
// Kernel 2: suffix sums over k for vz and c (tiny)
// =============================================================================
__global__ __launch_bounds__(256) void prefix_kernel()
{
    int idx = blockIdx.x * 256 + threadIdx.x;
    if (idx < 128 * 64) {
        int e = idx >> 6, i = idx & 63;
        float run = 0.f;
        #pragma unroll
        for (int k = 15; k >= 0; k--) {
            run += g_Vz[k][e][i];
            g_VzSS[k][e][i] = run;
        }
    } else if (idx < 128 * 64 + 64) {
        int i = idx - 128 * 64;
        float run = 0.f;
        #pragma unroll
        for (int k = 15; k >= 0; k--) {
            run += g_C[k][i];
            g_CSS[k][i] = run;
        }
    }
}

// =============================================================================
// Kernel 3: main fused GEMM (proven 208us config) + embedded W1->infl copy.
// GEMM: tile 128 t x 64 i per block; per thread 8 t x 4 i; FMA-pipe bound,
// DRAM was 3% idle -> each block also streams 2 W1 chunks (2x384KB) to infl,
// 12 float4/thread per compute phase, hidden under the FFMA2 work.
// =============================================================================
#define TT 128
#define XR 64
#define ZR 64
#define CHUNK4 24576                   // float4 per (i,k) W1 chunk
#define CPT    192                     // float4 copied per thread per block

__device__ __forceinline__ void copy_step(
    const float4* __restrict__ s0, float4* __restrict__ d0,
    const float4* __restrict__ s1, float4* __restrict__ d1,
    int tid, int& c)
{
    #pragma unroll
    for (int g = 0; g < 3; g++) {
        if (c >= CPT) break;
        int j0 = (c + 0) * 256 + tid;
        int j1 = (c + 1) * 256 + tid;
        int j2 = (c + 2) * 256 + tid;
        int j3 = (c + 3) * 256 + tid;
        float4 v0 = (j0 < CHUNK4) ? s0[j0] : s1[j0 - CHUNK4];
        float4 v1 = (j1 < CHUNK4) ? s0[j1] : s1[j1 - CHUNK4];
        float4 v2 = (j2 < CHUNK4) ? s0[j2] : s1[j2 - CHUNK4];
        float4 v3 = (j3 < CHUNK4) ? s0[j3] : s1[j3 - CHUNK4];
        if (j0 < CHUNK4) d0[j0] = v0; else d1[j0 - CHUNK4] = v0;
        if (j1 < CHUNK4) d0[j1] = v1; else d1[j1 - CHUNK4] = v1;
        if (j2 < CHUNK4) d0[j2] = v2; else d1[j2 - CHUNK4] = v2;
        if (j3 < CHUNK4) d0[j3] = v3; else d1[j3 - CHUNK4] = v3;
        c += 4;
    }
}

__device__ __forceinline__ void compute_chunk(
    const float* __restrict__ abase,           // 8 rows, stride 64
    const float* __restrict__ wbase, int ibase, u64 (&acc)[8][2])
{
    const float4* a4 = (const float4*)abase;   // row r at a4 + r*16
    const float* wp  = wbase + ibase;
    #pragma unroll 2
    for (int kd4 = 0; kd4 < 16; kd4++) {
        float4 av[8];
        #pragma unroll
        for (int r = 0; r < 8; r++) av[r] = a4[r * 16 + kd4];
        #pragma unroll
        for (int j = 0; j < 4; j++) {
            ulonglong2 w = *(const ulonglong2*)(wp + (kd4 * 4 + j) * 64);
            #pragma unroll
            for (int r = 0; r < 8; r++) {
                float a_s = (j == 0) ? av[r].x : (j == 1) ? av[r].y
                          : (j == 2) ? av[r].z : av[r].w;
                u64 a = pack2(a_s);
                acc[r][0] = ffma2(a, w.x, acc[r][0]);
                acc[r][1] = ffma2(a, w.y, acc[r][1]);
            }
        }
    }
}

__device__ __forceinline__ void load_wchunk(const float* __restrict__ gsrc,
                                            float* __restrict__ sdst, int tid)
{
    const float4* s = (const float4*)gsrc;
    float4*       d = (float4*)sdst;
    #pragma unroll
    for (int r = 0; r < 4; r++) d[tid + 256 * r] = s[tid + 256 * r];
}

__global__ __launch_bounds__(256, 2) void main_kernel(
    const float* __restrict__ z, const float* __restrict__ x,
    const float* __restrict__ W1,
    float* __restrict__ out, float* __restrict__ infl)
{
    extern __shared__ float sm[];
    float* s_x = sm;                       // [144][64]
    float* s_z = s_x + 144 * XR;           // [128][64]
    float* s_w = s_z + 128 * ZR;           // [2][64*64]
    float* s_c = s_w + 2 * 4096;           // [64]

    int b  = blockIdx.y;
    int t0 = blockIdx.x * TT;
    int tid = threadIdx.x;
    int ig = tid & 15;                     // 16 i-groups x 4 i
    int tg = tid >> 4;                     // 16 t-groups x 8 t
    int tbase = tg * 8;
    int ibase = ig * 4;

    // ---- embedded-copy setup: this block owns W1 chunks 2*bid, 2*bid+1 ----
    int bid = blockIdx.y * 16 + blockIdx.x;        // 0..511
    int cb0 = bid * 2, cb1 = cb0 + 1;
    const float4* cs0 = (const float4*)W1 + (size_t)cb0 * CHUNK4;
    const float4* cs1 = (const float4*)W1 + (size_t)cb1 * CHUNK4;
    float4* cd0 = (float4*)infl + (size_t)((cb0 & 15) * 64 + (cb0 >> 4)) * CHUNK4;
    float4* cd1 = (float4*)infl + (size_t)((cb1 & 15) * 64 + (cb1 >> 4)) * CHUNK4;
    int cpos = 0;

    // ---- phase 0: x tile (zero-padded), z half 0, w buf0 = VzFull[0:64] ----
    const float4* x4 = (const float4*)(x + (size_t)b * T_ * XD);
    float4* sx4 = (float4*)s_x;
    #pragma unroll
    for (int it = 0; it < 9; it++) {
        int idx = tid + 256 * it;          // < 2304
        int col = idx >> 4, dq = idx & 15;
        int gt = t0 - TAU + col;
        float4 v = make_float4(0.f, 0.f, 0.f, 0.f);
        if (gt >= 0) v = x4[(size_t)gt * 16 + dq];
        sx4[col * 16 + dq] = v;
    }
    const float4* z4 = (const float4*)(z + (size_t)b * T_ * ZD);
    float4* sz4 = (float4*)s_z;
    #pragma unroll
    for (int it = 0; it < 8; it++) {
        int idx = tid + 256 * it;          // < 2048
        int tl = idx >> 4, eq = idx & 15;
        sz4[tl * 16 + eq] = z4[(size_t)(t0 + tl) * 32 + eq];
    }
    load_wchunk(&g_VzSS[0][0][0], s_w, tid);
    if (tid < 64) s_c[tid] = g_CSS[0][tid];
    __syncthreads();

    u64 acc[8][2];
    #pragma unroll
    for (int r = 0; r < 8; r++) { acc[r][0] = 0ull; acc[r][1] = 0ull; }

    // ---- z half 0, prefetch half-1 weights ----
    load_wchunk(&g_VzSS[0][64][0], s_w + 4096, tid);
    copy_step(cs0, cd0, cs1, cd1, tid, cpos);
    compute_chunk(s_z + tbase * ZR, s_w, ibase, acc);
    __syncthreads();

    // ---- reload z half 1, prefetch Vx[0] into buf0 ----
    #pragma unroll
    for (int it = 0; it < 8; it++) {
        int idx = tid + 256 * it;
        int tl = idx >> 4, eq = idx & 15;
        sz4[tl * 16 + eq] = z4[(size_t)(t0 + tl) * 32 + 16 + eq];
    }
    load_wchunk(&g_Vx[0][0][0], s_w, tid);
    __syncthreads();

    // ---- z half 1 ----
    copy_step(cs0, cd0, cs1, cd1, tid, cpos);
    compute_chunk(s_z + tbase * ZR, s_w + 4096, ibase, acc);
    __syncthreads();

    // ---- 16 x-tap chunks, double-buffered weights, copy slice per tap ----
    for (int kk = 0; kk < 16; kk++) {
        if (kk < 15)
            load_wchunk(&g_Vx[kk + 1][0][0], s_w + ((kk + 1) & 1) * 4096, tid);
        copy_step(cs0, cd0, cs1, cd1, tid, cpos);
        compute_chunk(s_x + (tbase + 15 - kk) * XR,
                      s_w + (kk & 1) * 4096, ibase, acc);
        __syncthreads();
    }

    // ---- epilogue ----
    float c0 = s_c[ibase + 0], c1 = s_c[ibase + 1];
    float c2 = s_c[ibase + 2], c3 = s_c[ibase + 3];
    #pragma unroll
    for (int r = 0; r < 8; r++) {
        int t = t0 + tbase + r;
        F2U u0; u0.u = acc[r][0];
        F2U u1; u1.u = acc[r][1];
        float4* op = (float4*)(out + ((size_t)b * T_ + t) * XD + ibase);
        op[0] = make_float4(u0.f.x + c0, u0.f.y + c1, u1.f.x + c2, u1.f.y + c3);
    }
}

// =============================================================================
// Kernel 4: fixup for t < 16 (subtract invalid-k sz + c via suffix sums)
// =============================================================================
__global__ __launch_bounds__(128) void fixup_kernel(
    const float* __restrict__ z, float* __restrict__ out)
{
    int t = blockIdx.x;      // 0..15
    int b = blockIdx.y;      // 0..31
    __shared__ float s_zrow[128];
    __shared__ float s_part[64];

    int tid = threadIdx.x;
    s_zrow[tid] = z[((size_t)b * T_ + t) * ZD + tid];
    __syncthreads();

    int i    = tid & 63;
    int half = tid >> 6;
    const float* w = &g_VzSS[t][half * 64][i];
    float acc = 0.f;
    #pragma unroll
    for (int e0 = 0; e0 < 64; e0++)
        acc += s_zrow[half * 64 + e0] * w[e0 * 64];

    if (half == 1) s_part[i] = acc;
    __syncthreads();
    if (half == 0) {
        float corr = acc + s_part[i] + g_CSS[t][i];
        out[((size_t)b * T_ + t) * XD + i] -= corr;
    }
}

// =============================================================================
extern "C" void kernel_launch(void* const* d_in, const int* in_sizes, int n_in,
                              void* d_out, int out_size)
{
    const float* z  = (const float*)d_in[0];
    const float* x  = (const float*)d_in[1];
    const float* W1 = (const float*)d_in[2];
    const float* b1 = (const float*)d_in[3];
    const float* W2 = (const float*)d_in[4];
    const float* b2 = (const float*)d_in[5];
    float* out  = (float*)d_out;
    float* infl = out + (size_t)B_ * T_ * XD;

    vc_kernel<<<1024, 256>>>(W1, b1, W2, b2);
    prefix_kernel<<<33, 256>>>();

    int smem = (144 * XR + 128 * ZR + 2 * 4096 + 64) * (int)sizeof(float);
    cudaFuncSetAttribute(main_kernel, cudaFuncAttributeMaxDynamicSharedMemorySize, smem);
    main_kernel<<<dim3(16, 32), 256, smem>>>(z, x, W1, out, infl);

    fixup_kernel<<<dim3(16, 32), 128>>>(z, out);
}